// round 10
// baseline (speedup 1.0000x reference)
#include <cuda_runtime.h>
#include <math.h>
#include <stdint.h>

// ---------------- constants ----------------
#define BB   4
#define CC   64
#define HH   256
#define WW   256
#define NN   65536      // HH*WW
#define HEADS 8
#define CHD  8
#define HIDD 170
#define HID2 340
#define C3   192
#define C2   128
#define BN   262144     // BB*NN

// ---------------- scratch (static device memory; allocation-free) ----------------
__device__ float d_y   [BB*CC*NN];     // LN1 out -> comb -> LN2 out (reused)
__device__ float d_xT  [BB*CC*NN];     // input transposed to (B,C,N)
__device__ float d_xi1 [BB*CC*NN];     // after attention residual
__device__ float d_g1  [BB*CC*NN];     // gelu(x1)
__device__ float d_big [BB*HID2*NN];   // qkv_pre (192ch) then FFN hidden (340ch)
__device__ float d_qkv [BB*C3*NN];     // depthwise qkv (raw; norms fused into consumers)
__device__ float d_u   [BB*C2*NN];     // dw1 out (128ch)
__device__ float d_g2  [BB*HIDD*NN];   // gated FFN hidden (170ch)
__device__ float d_ref [BB*HEADS*NN];  // sigmoid(refine)
__device__ float d_meanpart[BB*CC*64];
__device__ float d_xsca[BB*CC];
__device__ float d_attnpart[32*64*80];
__device__ float d_attnm[32*80];

__device__ __forceinline__ float gelu_exact(float x) {
    return 0.5f * x * (1.f + erff(x * 0.70710678118654752f));
}

// warp mapping: 4 rows x 8 col-groups per warp -> conflict-free LDS.128 on 40-float rows
__device__ __forceinline__ void tmap(int tid, int& row, int& cg) {
    int lane = tid & 31;
    cg  = lane & 7;
    row = ((tid >> 5) << 2) | ((lane >> 3) & 3);
}

// ---------------- packed f32x2 helpers ----------------
__device__ __forceinline__ void fma2(unsigned long long& a, unsigned long long b, unsigned long long c) {
    asm("fma.rn.f32x2 %0, %1, %2, %0;" : "+l"(a) : "l"(b), "l"(c));
}
__device__ __forceinline__ void add2(unsigned long long& a, unsigned long long b) {
    asm("add.rn.f32x2 %0, %0, %1;" : "+l"(a) : "l"(b));
}
__device__ __forceinline__ unsigned long long splat2(float v) {
    unsigned long long s;
    asm("mov.b64 %0, {%1, %1};" : "=l"(s) : "f"(v));
    return s;
}

// ================= f32x2 1x1-conv GEMM =================
// 512 threads, 256 pixels/block. 16 warps: half = wi>>3 (pixel half), og = wi&7
// (8-output group). Thread computes 8 outputs x 4 pixels as f32x2 pairs.
// Weights staged into smem pre-splatted ((w,w) u64) -> zero packing in inner loop.
__device__ __forceinline__ void gemm_compute(const float* __restrict__ in_s,
                                             const unsigned long long* __restrict__ w2t,
                                             int kc, int og, int px,
                                             unsigned long long acc[8][2])
{
    #pragma unroll 4
    for (int k = 0; k < kc; k++) {
        ulonglong2 xv = *(const ulonglong2*)&in_s[k*256 + px];
        const ulonglong2* wp = (const ulonglong2*)&w2t[k*64 + og*8];
        #pragma unroll
        for (int jj = 0; jj < 4; jj++) {
            ulonglong2 wv = wp[jj];   // broadcast LDS.128: 2 splatted weights
            fma2(acc[2*jj+0][0], wv.x, xv.x); fma2(acc[2*jj+0][1], wv.x, xv.y);
            fma2(acc[2*jj+1][0], wv.y, xv.x); fma2(acc[2*jj+1][1], wv.y, xv.y);
        }
    }
}

template<int INC, int INCP, int OUT, int RESID>
__global__ void __launch_bounds__(512) gemm2_kernel(
        const float* __restrict__ in, const float* __restrict__ w,
        float* __restrict__ out, const float* __restrict__ resid)
{
    extern __shared__ float sm[];
    float* in_s = sm;                                        // 64 x 256 floats (64KB)
    unsigned long long* w2t = (unsigned long long*)(sm + 64*256);  // [64][64] u64 (32KB)
    const int tid = threadIdx.x;
    const int wi = tid >> 5, lane = tid & 31;
    const int half = wi >> 3, og = wi & 7;
    const int bz = blockIdx.z;
    const int pix0 = blockIdx.x * 256;
    const int px = half*128 + lane*4;

    if (INCP <= 64) {
        // ---- stage input once ----
        for (int idx = tid; idx < 64*64; idx += 512) {
            int k = idx >> 6, p = (idx & 63) * 4;
            float4 v = make_float4(0.f,0.f,0.f,0.f);
            if (k < INC) v = *(const float4*)&in[((size_t)(bz*INC + k))*NN + pix0 + p];
            *(float4*)&in_s[k*256 + p] = v;
        }
        for (int ob = 0; ob < OUT; ob += 64) {
            __syncthreads();   // first iter: covers in_s staging; later: prior compute done
            for (int idx = tid; idx < 64*64; idx += 512) {
                int k = idx >> 6, o = idx & 63;
                float v = (k < INC && ob + o < OUT) ? w[(size_t)(ob+o)*INC + k] : 0.f;
                w2t[k*64 + o] = splat2(v);
            }
            __syncthreads();
            unsigned long long acc[8][2] = {};
            gemm_compute(in_s, w2t, 64, og, px, acc);
            #pragma unroll
            for (int j = 0; j < 8; j++) {
                int o = ob + og*8 + j;
                if ((OUT % 64 != 0) && o >= OUT) break;
                size_t base = ((size_t)(bz*OUT + o))*NN + pix0 + px;
                if (RESID) {
                    ulonglong2 rr = *(const ulonglong2*)&resid[base];
                    add2(acc[j][0], rr.x); add2(acc[j][1], rr.y);
                }
                ulonglong2 st; st.x = acc[j][0]; st.y = acc[j][1];
                *(ulonglong2*)&out[base] = st;
            }
        }
    } else {
        // ---- k-chunked path (single 64-output chunk) ----
        unsigned long long acc[8][2] = {};
        for (int k0 = 0; k0 < INCP; k0 += 64) {
            const int kc = (INCP - k0 >= 64) ? 64 : (INCP - k0);
            __syncthreads();
            for (int idx = tid; idx < kc*64; idx += 512) {
                int k = idx >> 6, p = (idx & 63) * 4;
                int row = k0 + k;
                float4 v = make_float4(0.f,0.f,0.f,0.f);
                if (row < INC) v = *(const float4*)&in[((size_t)(bz*INC + row))*NN + pix0 + p];
                *(float4*)&in_s[k*256 + p] = v;
            }
            for (int idx = tid; idx < kc*64; idx += 512) {
                int k = idx >> 6, o = idx & 63;
                int row = k0 + k;
                float v = (row < INC && o < OUT) ? w[(size_t)o*INC + row] : 0.f;
                w2t[k*64 + o] = splat2(v);
            }
            __syncthreads();
            gemm_compute(in_s, w2t, kc, og, px, acc);
        }
        #pragma unroll
        for (int j = 0; j < 8; j++) {
            int o = og*8 + j;
            if (o >= OUT) break;
            size_t base = ((size_t)(bz*OUT + o))*NN + pix0 + px;
            if (RESID) {
                ulonglong2 rr = *(const ulonglong2*)&resid[base];
                add2(acc[j][0], rr.x); add2(acc[j][1], rr.y);
            }
            ulonglong2 st; st.x = acc[j][0]; st.y = acc[j][1];
            *(ulonglong2*)&out[base] = st;
        }
    }
}

// ---------------- BiasFree LayerNorm ----------------
template<int LAYOUT>
__global__ void ln_kernel(const float* __restrict__ in, const float* __restrict__ w,
                          float* __restrict__ out, float* __restrict__ xT)
{
    int gid = blockIdx.x * 256 + threadIdx.x;
    int b = gid >> 16;
    int n = gid & (NN - 1);
    float v[CC];
    if (LAYOUT == 0) {
        const float4* p = reinterpret_cast<const float4*>(in + (size_t)gid * CC);
        #pragma unroll
        for (int i = 0; i < 16; i++) {
            float4 t = p[i];
            v[4*i] = t.x; v[4*i+1] = t.y; v[4*i+2] = t.z; v[4*i+3] = t.w;
        }
    } else {
        #pragma unroll
        for (int c = 0; c < CC; c++) v[c] = in[((size_t)b*CC + c)*NN + n];
    }
    float s = 0.f, s2 = 0.f;
    #pragma unroll
    for (int c = 0; c < CC; c++) { s += v[c]; s2 += v[c]*v[c]; }
    float mean = s * (1.f / CC);
    float var  = s2 * (1.f / CC) - mean * mean;
    float inv  = rsqrtf(var + 1e-5f);
    #pragma unroll
    for (int c = 0; c < CC; c++) {
        size_t o = ((size_t)b*CC + c)*NN + n;
        out[o] = v[c] * inv * __ldg(&w[c]);
        if (LAYOUT == 0) xT[o] = v[c];
    }
}

// ---------------- channel mean of LN1 output (stage 1) ----------------
__global__ void mean1_kernel(const float* __restrict__ y, float* __restrict__ part)
{
    int chunk = blockIdx.x;
    int bc    = blockIdx.y;
    size_t base = (size_t)bc * NN + chunk * 1024;
    float s = 0.f;
    #pragma unroll
    for (int i = 0; i < 4; i++) s += y[base + i*256 + threadIdx.x];
    __shared__ float red[256];
    red[threadIdx.x] = s; __syncthreads();
    for (int off = 128; off; off >>= 1) {
        if (threadIdx.x < off) red[threadIdx.x] += red[threadIdx.x + off];
        __syncthreads();
    }
    if (threadIdx.x == 0) part[bc*64 + chunk] = red[0];
}

__global__ void xsca_kernel(const float* __restrict__ part, const float* __restrict__ sw,
                            const float* __restrict__ sb, float* __restrict__ xsca)
{
    __shared__ float m[CC];
    int b = blockIdx.x, c = threadIdx.x;
    float s = 0.f;
    for (int k = 0; k < 64; k++) s += part[(b*CC + c)*64 + k];
    m[c] = s * (1.f / NN);
    __syncthreads();
    float a = __ldg(&sb[c]);
    for (int i = 0; i < CC; i++) a += __ldg(&sw[c*CC + i]) * m[i];
    xsca[b*CC + c] = a;
}

// ---------------- depthwise 3x3 (pad 1), 32x32 tile, 4 cols/thread ----------------
template<int NCH>
__global__ void dw3_kernel(const float* __restrict__ in, const float* __restrict__ w,
                           float* __restrict__ out)
{
    int z = blockIdx.z; int b = z / NCH; int ch = z - b*NCH;
    const float* plane = in + ((size_t)b*NCH + ch) * NN;
    __shared__ float raw[34*40];
    int row, cg; tmap(threadIdx.x, row, cg);
    int gx0 = blockIdx.x * 32, gy0 = blockIdx.y * 32;
    for (int idx = threadIdx.x; idx < 34*34; idx += 256) {
        int r = idx / 34, c = idx - r*34;
        int gy = gy0 - 1 + r, gx = gx0 - 1 + c;
        raw[r*40 + c] = (gy >= 0 && gy < HH && gx >= 0 && gx < WW) ? plane[gy*WW + gx] : 0.f;
    }
    float wr[9];
    #pragma unroll
    for (int i = 0; i < 9; i++) wr[i] = __ldg(&w[ch*9 + i]);
    __syncthreads();
    float acc[4] = {0.f,0.f,0.f,0.f};
    #pragma unroll
    for (int ky = 0; ky < 3; ky++) {
        const float4* rp = (const float4*)&raw[(row+ky)*40 + cg*4];
        float f[8];
        *(float4*)&f[0] = rp[0]; *(float4*)&f[4] = rp[1];
        #pragma unroll
        for (int kx = 0; kx < 3; kx++)
            #pragma unroll
            for (int cx = 0; cx < 4; cx++) acc[cx] += wr[ky*3+kx]*f[cx+kx];
    }
    size_t o = ((size_t)b*NCH + ch)*NN + (size_t)(gy0+row)*WW + gx0 + cg*4;
    *(float4*)&out[o] = make_float4(acc[0],acc[1],acc[2],acc[3]);
}

// ---------------- grouped conv dw2 (2 in / 1 out per group) + GELU ----------------
__global__ void dw2gelu_kernel(const float* __restrict__ u, const float* __restrict__ w,
                               float* __restrict__ g1)
{
    int z = blockIdx.z; int b = z / CC; int c = z - b*CC;
    __shared__ float raw[2][34*40];
    int row, cg; tmap(threadIdx.x, row, cg);
    int gx0 = blockIdx.x * 32, gy0 = blockIdx.y * 32;
    for (int idx = threadIdx.x; idx < 2*34*34; idx += 256) {
        int j = idx / (34*34); int rem = idx - j*34*34;
        int r = rem / 34, cc2 = rem - r*34;
        int gy = gy0 - 1 + r, gx = gx0 - 1 + cc2;
        raw[j][r*40 + cc2] = (gy >= 0 && gy < HH && gx >= 0 && gx < WW)
                             ? u[((size_t)b*C2 + 2*c + j)*NN + gy*WW + gx] : 0.f;
    }
    float wr[2][9];
    #pragma unroll
    for (int j = 0; j < 2; j++)
        #pragma unroll
        for (int i = 0; i < 9; i++) wr[j][i] = __ldg(&w[(c*2 + j)*9 + i]);
    __syncthreads();
    float acc[4] = {0.f,0.f,0.f,0.f};
    #pragma unroll
    for (int j = 0; j < 2; j++)
        #pragma unroll
        for (int ky = 0; ky < 3; ky++) {
            const float4* rp = (const float4*)&raw[j][(row+ky)*40 + cg*4];
            float f[8];
            *(float4*)&f[0] = rp[0]; *(float4*)&f[4] = rp[1];
            #pragma unroll
            for (int kx = 0; kx < 3; kx++)
                #pragma unroll
                for (int cx = 0; cx < 4; cx++) acc[cx] += wr[j][ky*3+kx]*f[cx+kx];
        }
    size_t o = ((size_t)b*CC + c)*NN + (size_t)(gy0+row)*WW + gx0 + cg*4;
    *(float4*)&g1[o] = make_float4(gelu_exact(acc[0]),gelu_exact(acc[1]),
                                   gelu_exact(acc[2]),gelu_exact(acc[3]));
}

// ---------------- FFN depthwise 3x3 + gated GELU ----------------
__global__ void ffndw_kernel(const float* __restrict__ h, const float* __restrict__ w,
                             float* __restrict__ g2)
{
    int z = blockIdx.z; int b = z / HIDD; int i = z - b*HIDD;
    const float* p0 = h + ((size_t)b*HID2 + i) * NN;
    const float* p1 = h + ((size_t)b*HID2 + HIDD + i) * NN;
    __shared__ float raw[2][34*40];
    int row, cg; tmap(threadIdx.x, row, cg);
    int gx0 = blockIdx.x * 32, gy0 = blockIdx.y * 32;
    for (int idx = threadIdx.x; idx < 2*34*34; idx += 256) {
        int j = idx / (34*34); int rem = idx - j*34*34;
        int r = rem / 34, cc2 = rem - r*34;
        int gy = gy0 - 1 + r, gx = gx0 - 1 + cc2;
        const float* pl = j ? p1 : p0;
        raw[j][r*40 + cc2] = (gy >= 0 && gy < HH && gx >= 0 && gx < WW) ? pl[gy*WW + gx] : 0.f;
    }
    float w0[9], w1[9];
    #pragma unroll
    for (int t = 0; t < 9; t++) { w0[t] = __ldg(&w[i*9 + t]); w1[t] = __ldg(&w[(HIDD+i)*9 + t]); }
    __syncthreads();
    float a0[4] = {0.f,0.f,0.f,0.f}, a1[4] = {0.f,0.f,0.f,0.f};
    #pragma unroll
    for (int ky = 0; ky < 3; ky++) {
        const float4* rp0 = (const float4*)&raw[0][(row+ky)*40 + cg*4];
        const float4* rp1 = (const float4*)&raw[1][(row+ky)*40 + cg*4];
        float f0[8], f1[8];
        *(float4*)&f0[0] = rp0[0]; *(float4*)&f0[4] = rp0[1];
        *(float4*)&f1[0] = rp1[0]; *(float4*)&f1[4] = rp1[1];
        #pragma unroll
        for (int kx = 0; kx < 3; kx++)
            #pragma unroll
            for (int cx = 0; cx < 4; cx++) {
                a0[cx] += w0[ky*3+kx]*f0[cx+kx];
                a1[cx] += w1[ky*3+kx]*f1[cx+kx];
            }
    }
    size_t o = ((size_t)b*HIDD + i)*NN + (size_t)(gy0+row)*WW + gx0 + cg*4;
    *(float4*)&g2[o] = make_float4(gelu_exact(a0[0])*a1[0], gelu_exact(a0[1])*a1[1],
                                   gelu_exact(a0[2])*a1[2], gelu_exact(a0[3])*a1[3]);
}

// ---------------- attention reductions (k@v, ksum, vsum) with fused k-norm ----------------
__global__ void attnred1_kernel(const float* __restrict__ qkv, float* __restrict__ part)
{
    int bh = blockIdx.y; int b = bh >> 3; int hh = bh & 7;
    int chunk = blockIdx.x;
    size_t kb = ((size_t)b*C3 + CC + hh*CHD)*NN;
    size_t vb = ((size_t)b*C3 + 2*CC + hh*CHD)*NN;
    float kv[8][8]; float ks[8]; float vs[8];
    #pragma unroll
    for (int i = 0; i < 8; i++) {
        ks[i] = 0.f; vs[i] = 0.f;
        #pragma unroll
        for (int j = 0; j < 8; j++) kv[i][j] = 0.f;
    }
    for (int it = 0; it < 4; it++) {
        int n = chunk*1024 + it*256 + threadIdx.x;
        float kk[8], vv[8]; float ks2 = 0.f;
        #pragma unroll
        for (int i = 0; i < 8; i++) {
            kk[i] = qkv[kb + i*NN + n]; ks2 += kk[i]*kk[i];
            vv[i] = qkv[vb + i*NN + n];
        }
        float ksc = 1.f / (sqrtf(ks2) + 1e-6f);
        #pragma unroll
        for (int i = 0; i < 8; i++) {
            kk[i] *= ksc;
            ks[i] += kk[i]; vs[i] += vv[i];
            #pragma unroll
            for (int j = 0; j < 8; j++) kv[i][j] += kk[i]*vv[j];
        }
    }
    __shared__ float red[8][80];
    int lane = threadIdx.x & 31, wid = threadIdx.x >> 5;
    #pragma unroll
    for (int idx = 0; idx < 80; idx++) {
        float v;
        if (idx < 64) v = kv[idx >> 3][idx & 7];
        else if (idx < 72) v = ks[idx - 64];
        else v = vs[idx - 72];
        #pragma unroll
        for (int off = 16; off; off >>= 1) v += __shfl_down_sync(0xffffffffu, v, off);
        if (lane == 0) red[wid][idx] = v;
    }
    __syncthreads();
    if (threadIdx.x < 80) {
        float s = 0.f;
        #pragma unroll
        for (int w2 = 0; w2 < 8; w2++) s += red[w2][threadIdx.x];
        part[((size_t)bh*64 + chunk)*80 + threadIdx.x] = s;
    }
}

__global__ void attnred2_kernel(const float* __restrict__ part, float* __restrict__ attnm)
{
    int bh = blockIdx.x; int t = threadIdx.x;
    if (t < 80) {
        float s = 0.f;
        for (int c2 = 0; c2 < 64; c2++) s += part[((size_t)bh*64 + c2)*80 + t];
        attnm[bh*80 + t] = s;
    }
}

// ---------------- multi-window refine conv + sigmoid (fused q/k norm) ----------------
template<int WS>
__global__ void refine_kernel(const float* __restrict__ qkv, const float* __restrict__ w,
                              const float* __restrict__ bias, int head0, int nh,
                              float* __restrict__ refine)
{
    constexpr int R  = WS/2;
    constexpr int RR = 32 + 2*R;
    constexpr int PS = RR*40;
    extern __shared__ float sm[];
    float* wsm = sm + 16*PS;
    int z = blockIdx.z; int b = z / nh; int hw = z - b*nh; int hh = head0 + hw;
    int row, cg; tmap(threadIdx.x, row, cg);
    int gx0 = blockIdx.x*32, gy0 = blockIdx.y*32;
    for (int idx = threadIdx.x; idx < 16*RR*RR; idx += 256) {
        int ci = idx / (RR*RR); int rem = idx - ci*RR*RR;
        int r = rem / RR, c = rem - r*RR;
        int gy = gy0 - R + r, gx = gx0 - R + c;
        int chan = (ci < 8) ? (hh*CHD + ci) : (CC + hh*CHD + ci - 8);
        sm[ci*PS + r*40 + c] = (gy >= 0 && gy < HH && gx >= 0 && gx < WW)
                               ? qkv[((size_t)b*C3 + chan)*NN + gy*WW + gx] : 0.f;
    }
    for (int idx = threadIdx.x; idx < 16*WS*WS; idx += 256)
        wsm[idx] = __ldg(&w[hw*16*WS*WS + idx]);
    __syncthreads();
    for (int p = threadIdx.x; p < RR*RR; p += 256) {
        int r = p / RR, c = p - r*RR;
        int off = r*40 + c;
        float qv[8], kvv[8]; float qs = 0.f, ks2 = 0.f;
        #pragma unroll
        for (int i = 0; i < 8; i++) {
            qv[i] = sm[i*PS + off]; qs += qv[i]*qv[i];
            kvv[i] = sm[(8+i)*PS + off]; ks2 += kvv[i]*kvv[i];
        }
        float qsc = 1.f/(sqrtf(qs) + 1e-6f);
        float ksc = 1.f/(sqrtf(ks2) + 1e-6f);
        #pragma unroll
        for (int i = 0; i < 8; i++) {
            sm[i*PS + off] = qv[i]*qsc;
            sm[(8+i)*PS + off] = kvv[i]*ksc;
        }
    }
    __syncthreads();
    float acc[4] = {0.f,0.f,0.f,0.f};
    for (int ci = 0; ci < 16; ci++) {
        const float* pl = sm + ci*PS;
        #pragma unroll
        for (int ky = 0; ky < WS; ky++) {
            const float4* rp = (const float4*)&pl[(row+ky)*40 + cg*4];
            float f[12];
            *(float4*)&f[0] = rp[0]; *(float4*)&f[4] = rp[1];
            if (WS + 3 > 8) *(float4*)&f[8] = rp[2];
            #pragma unroll
            for (int kx = 0; kx < WS; kx++) {
                float wv = wsm[ci*WS*WS + ky*WS + kx];
                #pragma unroll
                for (int cx = 0; cx < 4; cx++) acc[cx] += wv*f[cx+kx];
            }
        }
    }
    float bb2 = __ldg(&bias[hw]);
    size_t o = ((size_t)(b*HEADS + hh))*NN + (size_t)(gy0+row)*WW + gx0 + cg*4;
    float4 r4;
    r4.x = 1.f/(1.f + expf(-(acc[0]+bb2)));
    r4.y = 1.f/(1.f + expf(-(acc[1]+bb2)));
    r4.z = 1.f/(1.f + expf(-(acc[2]+bb2)));
    r4.w = 1.f/(1.f + expf(-(acc[3]+bb2)));
    *(float4*)&refine[o] = r4;
}

// ---------------- combine (fused q-norm) ----------------
__global__ void combine_kernel(const float* __restrict__ qkv, const float* __restrict__ attnm,
                               const float* __restrict__ refine, const float* __restrict__ g1,
                               const float* __restrict__ xsca, const float* __restrict__ temp,
                               float* __restrict__ comb)
{
    int z = blockIdx.y; int b = z >> 3; int hh = z & 7;
    __shared__ float am[80];
    if (threadIdx.x < 80) am[threadIdx.x] = attnm[z*80 + threadIdx.x];
    __syncthreads();
    int n = blockIdx.x * 256 + threadIdx.x;
    float q[8]; float qs = 0.f;
    size_t qb = ((size_t)b*C3 + hh*CHD)*NN + n;
    #pragma unroll
    for (int i = 0; i < 8; i++) { q[i] = qkv[qb + i*NN]; qs += q[i]*q[i]; }
    float qsc = 1.f/(sqrtf(qs) + 1e-6f);
    #pragma unroll
    for (int i = 0; i < 8; i++) q[i] *= qsc;
    float den = (float)NN + 1e-6f;
    #pragma unroll
    for (int i = 0; i < 8; i++) den += q[i]*am[64 + i];
    float scale = __ldg(&temp[hh]) * refine[(size_t)z*NN + n] / den;
    #pragma unroll
    for (int j = 0; j < 8; j++) {
        float num = am[72 + j];
        #pragma unroll
        for (int i = 0; i < 8; i++) num += q[i]*am[i*8 + j];
        int c = hh*CHD + j;
        size_t o = ((size_t)b*CC + c)*NN + n;
        comb[o] = num * scale * __ldg(&xsca[b*CC + c]) * g1[o];
    }
}

// ---------------- launch ----------------
extern "C" void kernel_launch(void* const* d_in, const int* in_sizes, int n_in,
                              void* d_out, int out_size)
{
    const float* x      = (const float*)d_in[0];
    const float* ln1_w  = (const float*)d_in[1];
    const float* sca_w  = (const float*)d_in[2];
    const float* sca_b  = (const float*)d_in[3];
    const float* dw1_w  = (const float*)d_in[4];
    const float* dw2_w  = (const float*)d_in[5];
    const float* qkv_w  = (const float*)d_in[6];
    const float* qkv_dw = (const float*)d_in[7];
    const float* temp   = (const float*)d_in[8];
    const float* r3_w   = (const float*)d_in[9];
    const float* r3_b   = (const float*)d_in[10];
    const float* r5_w   = (const float*)d_in[11];
    const float* r5_b   = (const float*)d_in[12];
    const float* r7_w   = (const float*)d_in[13];
    const float* r7_b   = (const float*)d_in[14];
    const float* proj_w = (const float*)d_in[15];
    const float* ln2_w  = (const float*)d_in[16];
    const float* pin_w  = (const float*)d_in[17];
    const float* ffn_dw = (const float*)d_in[18];
    const float* pout_w = (const float*)d_in[19];
    float* out = (float*)d_out;

    float *py, *pxT, *pxi1, *pg1, *pbig, *pqkv, *pu, *pg2, *pref, *pmp, *pxsca, *ppart, *pattnm;
    cudaGetSymbolAddress((void**)&py,    d_y);
    cudaGetSymbolAddress((void**)&pxT,   d_xT);
    cudaGetSymbolAddress((void**)&pxi1,  d_xi1);
    cudaGetSymbolAddress((void**)&pg1,   d_g1);
    cudaGetSymbolAddress((void**)&pbig,  d_big);
    cudaGetSymbolAddress((void**)&pqkv,  d_qkv);
    cudaGetSymbolAddress((void**)&pu,    d_u);
    cudaGetSymbolAddress((void**)&pg2,   d_g2);
    cudaGetSymbolAddress((void**)&pref,  d_ref);
    cudaGetSymbolAddress((void**)&pmp,   d_meanpart);
    cudaGetSymbolAddress((void**)&pxsca, d_xsca);
    cudaGetSymbolAddress((void**)&ppart, d_attnpart);
    cudaGetSymbolAddress((void**)&pattnm,d_attnm);

    const int GSM = 64*256*4 + 64*64*8;   // 96KB dynamic smem
    cudaFuncSetAttribute((const void*)gemm2_kernel<CC, 64, C3,   0>, cudaFuncAttributeMaxDynamicSharedMemorySize, GSM);
    cudaFuncSetAttribute((const void*)gemm2_kernel<CC, 64, C2,   0>, cudaFuncAttributeMaxDynamicSharedMemorySize, GSM);
    cudaFuncSetAttribute((const void*)gemm2_kernel<CC, 64, CC,   1>, cudaFuncAttributeMaxDynamicSharedMemorySize, GSM);
    cudaFuncSetAttribute((const void*)gemm2_kernel<CC, 64, HID2, 0>, cudaFuncAttributeMaxDynamicSharedMemorySize, GSM);
    cudaFuncSetAttribute((const void*)gemm2_kernel<HIDD, 176, CC, 1>, cudaFuncAttributeMaxDynamicSharedMemorySize, GSM);
    cudaFuncSetAttribute(refine_kernel<3>, cudaFuncAttributeMaxDynamicSharedMemorySize, 16*(34*40)*4 + 16*9*4);
    cudaFuncSetAttribute(refine_kernel<5>, cudaFuncAttributeMaxDynamicSharedMemorySize, 16*(36*40)*4 + 16*25*4);
    cudaFuncSetAttribute(refine_kernel<7>, cudaFuncAttributeMaxDynamicSharedMemorySize, 16*(38*40)*4 + 16*49*4);

    // LN1 (+ transpose of input for residual)
    ln_kernel<0><<<BN/256, 256>>>(x, ln1_w, py, pxT);
    mean1_kernel<<<dim3(64, BB*CC), 256>>>(py, pmp);
    xsca_kernel<<<BB, CC>>>(pmp, sca_w, sca_b, pxsca);
    // 1x1 convs (f32x2 GEMM): qkv (192ch) and dw1 (128ch)
    gemm2_kernel<CC, 64, C3, 0><<<dim3(NN/256, 1, BB), 512, GSM>>>(py, qkv_w, pbig, nullptr);
    gemm2_kernel<CC, 64, C2, 0><<<dim3(NN/256, 1, BB), 512, GSM>>>(py, dw1_w, pu, nullptr);
    // depthwise 3x3 on qkv
    dw3_kernel<C3><<<dim3(8, 8, BB*C3), 256>>>(pbig, qkv_dw, pqkv);
    // grouped conv dw2 + gelu -> g1
    dw2gelu_kernel<<<dim3(8, 8, BB*CC), 256>>>(pu, dw2_w, pg1);
    // global reductions k@v, ksum, vsum (k-norm fused)
    attnred1_kernel<<<dim3(64, 32), 256>>>(pqkv, ppart);
    attnred2_kernel<<<32, 128>>>(ppart, pattnm);
    // refine conv + sigmoid (q/k-norm fused)
    refine_kernel<3><<<dim3(8, 8, BB*2), 256, 16*(34*40)*4 + 16*9*4>>>(pqkv, r3_w, r3_b, 0, 2, pref);
    refine_kernel<5><<<dim3(8, 8, BB*3), 256, 16*(36*40)*4 + 16*25*4>>>(pqkv, r5_w, r5_b, 2, 3, pref);
    refine_kernel<7><<<dim3(8, 8, BB*3), 256, 16*(38*40)*4 + 16*49*4>>>(pqkv, r7_w, r7_b, 5, 3, pref);
    // combine -> comb (reuse d_y)
    combine_kernel<<<dim3(NN/256, BB*HEADS), 256>>>(pqkv, pattnm, pref, pg1, pxsca, temp, py);
    // proj 1x1 + residual
    gemm2_kernel<CC, 64, CC, 1><<<dim3(NN/256, 1, BB), 512, GSM>>>(py, proj_w, pxi1, pxT);
    // LN2
    ln_kernel<1><<<BN/256, 256>>>(pxi1, ln2_w, py, nullptr);
    // FFN: pin 64->340
    gemm2_kernel<CC, 64, HID2, 0><<<dim3(NN/256, 1, BB), 512, GSM>>>(py, pin_w, pbig, nullptr);
    // FFN depthwise + gated gelu
    ffndw_kernel<<<dim3(8, 8, BB*HIDD), 256>>>(pbig, ffn_dw, pg2);
    // pout 170->64 + residual -> output
    gemm2_kernel<HIDD, 176, CC, 1><<<dim3(NN/256, 1, BB), 512, GSM>>>(pg2, pout_w, out, pxi1);
}

// round 11
// speedup vs baseline: 1.2673x; 1.2673x over previous
#include <cuda_runtime.h>
#include <math.h>
#include <stdint.h>

// ---------------- constants ----------------
#define BB   4
#define CC   64
#define HH   256
#define WW   256
#define NN   65536      // HH*WW
#define HEADS 8
#define CHD  8
#define HIDD 170
#define HID2 340
#define C3   192
#define C2   128
#define BN   262144     // BB*NN

// ---------------- scratch (static device memory; allocation-free) ----------------
__device__ float d_y   [BB*CC*NN];     // LN1 out -> comb -> LN2 out (reused)
__device__ float d_xT  [BB*CC*NN];     // input transposed to (B,C,N)
__device__ float d_xi1 [BB*CC*NN];     // after attention residual
__device__ float d_g1  [BB*CC*NN];     // gelu(x1)
__device__ float d_big [BB*HID2*NN];   // qkv_pre (192ch) then FFN hidden (340ch)
__device__ float d_qkv [BB*C3*NN];     // depthwise qkv (raw; norms fused into consumers)
__device__ float d_u   [BB*C2*NN];     // dw1 out (128ch)
__device__ float d_g2  [BB*HIDD*NN];   // gated FFN hidden (170ch)
__device__ float d_ref [BB*HEADS*NN];  // sigmoid(refine)
__device__ float d_meanpart[BB*CC*64];
__device__ float d_xsca[BB*CC];
__device__ float d_attnpart[32*64*80];
__device__ float d_attnm[32*80];

__device__ __forceinline__ float gelu_exact(float x) {
    return 0.5f * x * (1.f + erff(x * 0.70710678118654752f));
}

// warp mapping: 4 rows x 8 col-groups per warp -> conflict-free LDS.128 on 40-float rows
__device__ __forceinline__ void tmap(int tid, int& row, int& cg) {
    int lane = tid & 31;
    cg  = lane & 7;
    row = ((tid >> 5) << 2) | ((lane >> 3) & 3);
}

// ---------------- tf32 helpers ----------------
__device__ __forceinline__ uint32_t f2tf32(float f) {
    uint32_t u;
    asm("cvt.rna.tf32.f32 %0, %1;" : "=r"(u) : "f"(f));
    return u;
}
__device__ __forceinline__ void mma_tf32(float c[4], const uint32_t a[4], const uint32_t b[2]) {
    asm volatile(
        "mma.sync.aligned.m16n8k8.row.col.f32.tf32.tf32.f32 "
        "{%0,%1,%2,%3},{%4,%5,%6,%7},{%8,%9},{%0,%1,%2,%3};"
        : "+f"(c[0]), "+f"(c[1]), "+f"(c[2]), "+f"(c[3])
        : "r"(a[0]), "r"(a[1]), "r"(a[2]), "r"(a[3]), "r"(b[0]), "r"(b[1]));
}

// ================= mma.sync tf32 1x1-conv GEMM =================
// D[o][n] = sum_k W[o0+o][k] * X[k][pix0+n], per batch.
// Block: 256 thr (8 warps), tile M=64 x N=128. Warp: 32x32 (2 m-tiles x 4 n-tiles).
// A staged as w_s[o][k] stride 76 (conflict-free), B as in_s[k][n] stride 136.
#define SA 76
#define SB 136
template<int INC, int KCH, int OUT, int RESID>
__global__ void __launch_bounds__(256) mmagemm_kernel(
        const float* __restrict__ in, const float* __restrict__ w,
        float* __restrict__ out, const float* __restrict__ resid)
{
    extern __shared__ uint32_t dsm[];
    uint32_t* w_s  = dsm;            // 64 x SA
    uint32_t* in_s = dsm + 64*SA;    // 64 x SB
    const int tid = threadIdx.x;
    const int wi = tid >> 5, lane = tid & 31;
    const int g = lane >> 2, q = lane & 3;
    const int wm = wi & 1, wn = wi >> 1;
    const int o0 = blockIdx.y * 64;
    const int pix0 = blockIdx.x * 128;
    const int bz = blockIdx.z;

    float acc[2][4][4];
    #pragma unroll
    for (int mt = 0; mt < 2; mt++)
        #pragma unroll
        for (int nt = 0; nt < 4; nt++)
            #pragma unroll
            for (int i = 0; i < 4; i++) acc[mt][nt][i] = 0.f;

    for (int kc = 0; kc < KCH; kc++) {
        const int k0 = kc * 64;
        __syncthreads();
        // stage weights w_s[o][k]
        for (int idx = tid; idx < 64*64; idx += 256) {
            int o = idx >> 6, k = idx & 63;
            float v = 0.f;
            if ((o0 + o < OUT) && (k0 + k < INC)) v = w[(size_t)(o0 + o)*INC + k0 + k];
            w_s[o*SA + k] = f2tf32(v);
        }
        // stage inputs in_s[k][n]
        for (int idx = tid; idx < 64*32; idx += 256) {
            int k = idx >> 5, n = (idx & 31) * 4;
            float4 v = make_float4(0.f,0.f,0.f,0.f);
            if (k0 + k < INC) v = *(const float4*)&in[((size_t)(bz*INC + k0 + k))*NN + pix0 + n];
            in_s[k*SB + n + 0] = f2tf32(v.x);
            in_s[k*SB + n + 1] = f2tf32(v.y);
            in_s[k*SB + n + 2] = f2tf32(v.z);
            in_s[k*SB + n + 3] = f2tf32(v.w);
        }
        __syncthreads();
        #pragma unroll
        for (int ks = 0; ks < 8; ks++) {
            const int k = ks*8 + q;
            uint32_t a[2][4], b[4][2];
            #pragma unroll
            for (int mt = 0; mt < 2; mt++) {
                int o = wm*32 + mt*16 + g;
                a[mt][0] = w_s[o*SA + k];
                a[mt][1] = w_s[(o+8)*SA + k];
                a[mt][2] = w_s[o*SA + k + 4];
                a[mt][3] = w_s[(o+8)*SA + k + 4];
            }
            #pragma unroll
            for (int nt = 0; nt < 4; nt++) {
                int n = wn*32 + nt*8 + g;
                b[nt][0] = in_s[k*SB + n];
                b[nt][1] = in_s[(k+4)*SB + n];
            }
            #pragma unroll
            for (int mt = 0; mt < 2; mt++)
                #pragma unroll
                for (int nt = 0; nt < 4; nt++)
                    mma_tf32(acc[mt][nt], a[mt], b[nt]);
        }
    }

    // epilogue: c0,c1 -> (row g, cols 2q,2q+1); c2,c3 -> row g+8
    #pragma unroll
    for (int mt = 0; mt < 2; mt++) {
        #pragma unroll
        for (int nt = 0; nt < 4; nt++) {
            int o = o0 + wm*32 + mt*16 + g;
            int n = pix0 + wn*32 + nt*8 + q*2;
            if ((OUT % 64 == 0) || o < OUT) {
                size_t base = ((size_t)(bz*OUT + o))*NN + n;
                float2 v = make_float2(acc[mt][nt][0], acc[mt][nt][1]);
                if (RESID) { float2 r = *(const float2*)&resid[base]; v.x += r.x; v.y += r.y; }
                *(float2*)&out[base] = v;
            }
            if ((OUT % 64 == 0) || o + 8 < OUT) {
                size_t base = ((size_t)(bz*OUT + o + 8))*NN + n;
                float2 v = make_float2(acc[mt][nt][2], acc[mt][nt][3]);
                if (RESID) { float2 r = *(const float2*)&resid[base]; v.x += r.x; v.y += r.y; }
                *(float2*)&out[base] = v;
            }
        }
    }
}
#define GEMM_SMEM ((64*SA + 64*SB)*4)

// ---------------- BiasFree LayerNorm ----------------
template<int LAYOUT>
__global__ void ln_kernel(const float* __restrict__ in, const float* __restrict__ w,
                          float* __restrict__ out, float* __restrict__ xT)
{
    int gid = blockIdx.x * 256 + threadIdx.x;
    int b = gid >> 16;
    int n = gid & (NN - 1);
    float v[CC];
    if (LAYOUT == 0) {
        const float4* p = reinterpret_cast<const float4*>(in + (size_t)gid * CC);
        #pragma unroll
        for (int i = 0; i < 16; i++) {
            float4 t = p[i];
            v[4*i] = t.x; v[4*i+1] = t.y; v[4*i+2] = t.z; v[4*i+3] = t.w;
        }
    } else {
        #pragma unroll
        for (int c = 0; c < CC; c++) v[c] = in[((size_t)b*CC + c)*NN + n];
    }
    float s = 0.f, s2 = 0.f;
    #pragma unroll
    for (int c = 0; c < CC; c++) { s += v[c]; s2 += v[c]*v[c]; }
    float mean = s * (1.f / CC);
    float var  = s2 * (1.f / CC) - mean * mean;
    float inv  = rsqrtf(var + 1e-5f);
    #pragma unroll
    for (int c = 0; c < CC; c++) {
        size_t o = ((size_t)b*CC + c)*NN + n;
        out[o] = v[c] * inv * __ldg(&w[c]);
        if (LAYOUT == 0) xT[o] = v[c];
    }
}

// ---------------- channel mean of LN1 output (stage 1) ----------------
__global__ void mean1_kernel(const float* __restrict__ y, float* __restrict__ part)
{
    int chunk = blockIdx.x;
    int bc    = blockIdx.y;
    size_t base = (size_t)bc * NN + chunk * 1024;
    float s = 0.f;
    #pragma unroll
    for (int i = 0; i < 4; i++) s += y[base + i*256 + threadIdx.x];
    __shared__ float red[256];
    red[threadIdx.x] = s; __syncthreads();
    for (int off = 128; off; off >>= 1) {
        if (threadIdx.x < off) red[threadIdx.x] += red[threadIdx.x + off];
        __syncthreads();
    }
    if (threadIdx.x == 0) part[bc*64 + chunk] = red[0];
}

__global__ void xsca_kernel(const float* __restrict__ part, const float* __restrict__ sw,
                            const float* __restrict__ sb, float* __restrict__ xsca)
{
    __shared__ float m[CC];
    int b = blockIdx.x, c = threadIdx.x;
    float s = 0.f;
    for (int k = 0; k < 64; k++) s += part[(b*CC + c)*64 + k];
    m[c] = s * (1.f / NN);
    __syncthreads();
    float a = __ldg(&sb[c]);
    for (int i = 0; i < CC; i++) a += __ldg(&sw[c*CC + i]) * m[i];
    xsca[b*CC + c] = a;
}

// ---------------- depthwise 3x3 (pad 1), 32x32 tile, 4 cols/thread ----------------
template<int NCH>
__global__ void dw3_kernel(const float* __restrict__ in, const float* __restrict__ w,
                           float* __restrict__ out)
{
    int z = blockIdx.z; int b = z / NCH; int ch = z - b*NCH;
    const float* plane = in + ((size_t)b*NCH + ch) * NN;
    __shared__ float raw[34*40];
    int row, cg; tmap(threadIdx.x, row, cg);
    int gx0 = blockIdx.x * 32, gy0 = blockIdx.y * 32;
    for (int idx = threadIdx.x; idx < 34*34; idx += 256) {
        int r = idx / 34, c = idx - r*34;
        int gy = gy0 - 1 + r, gx = gx0 - 1 + c;
        raw[r*40 + c] = (gy >= 0 && gy < HH && gx >= 0 && gx < WW) ? plane[gy*WW + gx] : 0.f;
    }
    float wr[9];
    #pragma unroll
    for (int i = 0; i < 9; i++) wr[i] = __ldg(&w[ch*9 + i]);
    __syncthreads();
    float acc[4] = {0.f,0.f,0.f,0.f};
    #pragma unroll
    for (int ky = 0; ky < 3; ky++) {
        const float4* rp = (const float4*)&raw[(row+ky)*40 + cg*4];
        float f[8];
        *(float4*)&f[0] = rp[0]; *(float4*)&f[4] = rp[1];
        #pragma unroll
        for (int kx = 0; kx < 3; kx++)
            #pragma unroll
            for (int cx = 0; cx < 4; cx++) acc[cx] += wr[ky*3+kx]*f[cx+kx];
    }
    size_t o = ((size_t)b*NCH + ch)*NN + (size_t)(gy0+row)*WW + gx0 + cg*4;
    *(float4*)&out[o] = make_float4(acc[0],acc[1],acc[2],acc[3]);
}

// ---------------- grouped conv dw2 (2 in / 1 out per group) + GELU ----------------
__global__ void dw2gelu_kernel(const float* __restrict__ u, const float* __restrict__ w,
                               float* __restrict__ g1)
{
    int z = blockIdx.z; int b = z / CC; int c = z - b*CC;
    __shared__ float raw[2][34*40];
    int row, cg; tmap(threadIdx.x, row, cg);
    int gx0 = blockIdx.x * 32, gy0 = blockIdx.y * 32;
    for (int idx = threadIdx.x; idx < 2*34*34; idx += 256) {
        int j = idx / (34*34); int rem = idx - j*34*34;
        int r = rem / 34, cc2 = rem - r*34;
        int gy = gy0 - 1 + r, gx = gx0 - 1 + cc2;
        raw[j][r*40 + cc2] = (gy >= 0 && gy < HH && gx >= 0 && gx < WW)
                             ? u[((size_t)b*C2 + 2*c + j)*NN + gy*WW + gx] : 0.f;
    }
    float wr[2][9];
    #pragma unroll
    for (int j = 0; j < 2; j++)
        #pragma unroll
        for (int i = 0; i < 9; i++) wr[j][i] = __ldg(&w[(c*2 + j)*9 + i]);
    __syncthreads();
    float acc[4] = {0.f,0.f,0.f,0.f};
    #pragma unroll
    for (int j = 0; j < 2; j++)
        #pragma unroll
        for (int ky = 0; ky < 3; ky++) {
            const float4* rp = (const float4*)&raw[j][(row+ky)*40 + cg*4];
            float f[8];
            *(float4*)&f[0] = rp[0]; *(float4*)&f[4] = rp[1];
            #pragma unroll
            for (int kx = 0; kx < 3; kx++)
                #pragma unroll
                for (int cx = 0; cx < 4; cx++) acc[cx] += wr[j][ky*3+kx]*f[cx+kx];
        }
    size_t o = ((size_t)b*CC + c)*NN + (size_t)(gy0+row)*WW + gx0 + cg*4;
    *(float4*)&g1[o] = make_float4(gelu_exact(acc[0]),gelu_exact(acc[1]),
                                   gelu_exact(acc[2]),gelu_exact(acc[3]));
}

// ---------------- FFN depthwise 3x3 + gated GELU ----------------
__global__ void ffndw_kernel(const float* __restrict__ h, const float* __restrict__ w,
                             float* __restrict__ g2)
{
    int z = blockIdx.z; int b = z / HIDD; int i = z - b*HIDD;
    const float* p0 = h + ((size_t)b*HID2 + i) * NN;
    const float* p1 = h + ((size_t)b*HID2 + HIDD + i) * NN;
    __shared__ float raw[2][34*40];
    int row, cg; tmap(threadIdx.x, row, cg);
    int gx0 = blockIdx.x * 32, gy0 = blockIdx.y * 32;
    for (int idx = threadIdx.x; idx < 2*34*34; idx += 256) {
        int j = idx / (34*34); int rem = idx - j*34*34;
        int r = rem / 34, cc2 = rem - r*34;
        int gy = gy0 - 1 + r, gx = gx0 - 1 + cc2;
        const float* pl = j ? p1 : p0;
        raw[j][r*40 + cc2] = (gy >= 0 && gy < HH && gx >= 0 && gx < WW) ? pl[gy*WW + gx] : 0.f;
    }
    float w0[9], w1[9];
    #pragma unroll
    for (int t = 0; t < 9; t++) { w0[t] = __ldg(&w[i*9 + t]); w1[t] = __ldg(&w[(HIDD+i)*9 + t]); }
    __syncthreads();
    float a0[4] = {0.f,0.f,0.f,0.f}, a1[4] = {0.f,0.f,0.f,0.f};
    #pragma unroll
    for (int ky = 0; ky < 3; ky++) {
        const float4* rp0 = (const float4*)&raw[0][(row+ky)*40 + cg*4];
        const float4* rp1 = (const float4*)&raw[1][(row+ky)*40 + cg*4];
        float f0[8], f1[8];
        *(float4*)&f0[0] = rp0[0]; *(float4*)&f0[4] = rp0[1];
        *(float4*)&f1[0] = rp1[0]; *(float4*)&f1[4] = rp1[1];
        #pragma unroll
        for (int kx = 0; kx < 3; kx++)
            #pragma unroll
            for (int cx = 0; cx < 4; cx++) {
                a0[cx] += w0[ky*3+kx]*f0[cx+kx];
                a1[cx] += w1[ky*3+kx]*f1[cx+kx];
            }
    }
    size_t o = ((size_t)b*HIDD + i)*NN + (size_t)(gy0+row)*WW + gx0 + cg*4;
    *(float4*)&g2[o] = make_float4(gelu_exact(a0[0])*a1[0], gelu_exact(a0[1])*a1[1],
                                   gelu_exact(a0[2])*a1[2], gelu_exact(a0[3])*a1[3]);
}

// ---------------- attention reductions (k@v, ksum, vsum) with fused k-norm ----------------
__global__ void attnred1_kernel(const float* __restrict__ qkv, float* __restrict__ part)
{
    int bh = blockIdx.y; int b = bh >> 3; int hh = bh & 7;
    int chunk = blockIdx.x;
    size_t kb = ((size_t)b*C3 + CC + hh*CHD)*NN;
    size_t vb = ((size_t)b*C3 + 2*CC + hh*CHD)*NN;
    float kv[8][8]; float ks[8]; float vs[8];
    #pragma unroll
    for (int i = 0; i < 8; i++) {
        ks[i] = 0.f; vs[i] = 0.f;
        #pragma unroll
        for (int j = 0; j < 8; j++) kv[i][j] = 0.f;
    }
    for (int it = 0; it < 4; it++) {
        int n = chunk*1024 + it*256 + threadIdx.x;
        float kk[8], vv[8]; float ks2 = 0.f;
        #pragma unroll
        for (int i = 0; i < 8; i++) {
            kk[i] = qkv[kb + i*NN + n]; ks2 += kk[i]*kk[i];
            vv[i] = qkv[vb + i*NN + n];
        }
        float ksc = 1.f / (sqrtf(ks2) + 1e-6f);
        #pragma unroll
        for (int i = 0; i < 8; i++) {
            kk[i] *= ksc;
            ks[i] += kk[i]; vs[i] += vv[i];
            #pragma unroll
            for (int j = 0; j < 8; j++) kv[i][j] += kk[i]*vv[j];
        }
    }
    __shared__ float red[8][80];
    int lane = threadIdx.x & 31, wid = threadIdx.x >> 5;
    #pragma unroll
    for (int idx = 0; idx < 80; idx++) {
        float v;
        if (idx < 64) v = kv[idx >> 3][idx & 7];
        else if (idx < 72) v = ks[idx - 64];
        else v = vs[idx - 72];
        #pragma unroll
        for (int off = 16; off; off >>= 1) v += __shfl_down_sync(0xffffffffu, v, off);
        if (lane == 0) red[wid][idx] = v;
    }
    __syncthreads();
    if (threadIdx.x < 80) {
        float s = 0.f;
        #pragma unroll
        for (int w2 = 0; w2 < 8; w2++) s += red[w2][threadIdx.x];
        part[((size_t)bh*64 + chunk)*80 + threadIdx.x] = s;
    }
}

__global__ void attnred2_kernel(const float* __restrict__ part, float* __restrict__ attnm)
{
    int bh = blockIdx.x; int t = threadIdx.x;
    if (t < 80) {
        float s = 0.f;
        for (int c2 = 0; c2 < 64; c2++) s += part[((size_t)bh*64 + c2)*80 + t];
        attnm[bh*80 + t] = s;
    }
}

// ---------------- multi-window refine conv + sigmoid (fused q/k norm) ----------------
template<int WS>
__global__ void refine_kernel(const float* __restrict__ qkv, const float* __restrict__ w,
                              const float* __restrict__ bias, int head0, int nh,
                              float* __restrict__ refine)
{
    constexpr int R  = WS/2;
    constexpr int RR = 32 + 2*R;
    constexpr int PS = RR*40;
    extern __shared__ float sm[];
    float* wsm = sm + 16*PS;
    int z = blockIdx.z; int b = z / nh; int hw = z - b*nh; int hh = head0 + hw;
    int row, cg; tmap(threadIdx.x, row, cg);
    int gx0 = blockIdx.x*32, gy0 = blockIdx.y*32;
    for (int idx = threadIdx.x; idx < 16*RR*RR; idx += 256) {
        int ci = idx / (RR*RR); int rem = idx - ci*RR*RR;
        int r = rem / RR, c = rem - r*RR;
        int gy = gy0 - R + r, gx = gx0 - R + c;
        int chan = (ci < 8) ? (hh*CHD + ci) : (CC + hh*CHD + ci - 8);
        sm[ci*PS + r*40 + c] = (gy >= 0 && gy < HH && gx >= 0 && gx < WW)
                               ? qkv[((size_t)b*C3 + chan)*NN + gy*WW + gx] : 0.f;
    }
    for (int idx = threadIdx.x; idx < 16*WS*WS; idx += 256)
        wsm[idx] = __ldg(&w[hw*16*WS*WS + idx]);
    __syncthreads();
    for (int p = threadIdx.x; p < RR*RR; p += 256) {
        int r = p / RR, c = p - r*RR;
        int off = r*40 + c;
        float qv[8], kvv[8]; float qs = 0.f, ks2 = 0.f;
        #pragma unroll
        for (int i = 0; i < 8; i++) {
            qv[i] = sm[i*PS + off]; qs += qv[i]*qv[i];
            kvv[i] = sm[(8+i)*PS + off]; ks2 += kvv[i]*kvv[i];
        }
        float qsc = 1.f/(sqrtf(qs) + 1e-6f);
        float ksc = 1.f/(sqrtf(ks2) + 1e-6f);
        #pragma unroll
        for (int i = 0; i < 8; i++) {
            sm[i*PS + off] = qv[i]*qsc;
            sm[(8+i)*PS + off] = kvv[i]*ksc;
        }
    }
    __syncthreads();
    float acc[4] = {0.f,0.f,0.f,0.f};
    for (int ci = 0; ci < 16; ci++) {
        const float* pl = sm + ci*PS;
        #pragma unroll
        for (int ky = 0; ky < WS; ky++) {
            const float4* rp = (const float4*)&pl[(row+ky)*40 + cg*4];
            float f[12];
            *(float4*)&f[0] = rp[0]; *(float4*)&f[4] = rp[1];
            if (WS + 3 > 8) *(float4*)&f[8] = rp[2];
            #pragma unroll
            for (int kx = 0; kx < WS; kx++) {
                float wv = wsm[ci*WS*WS + ky*WS + kx];
                #pragma unroll
                for (int cx = 0; cx < 4; cx++) acc[cx] += wv*f[cx+kx];
            }
        }
    }
    float bb2 = __ldg(&bias[hw]);
    size_t o = ((size_t)(b*HEADS + hh))*NN + (size_t)(gy0+row)*WW + gx0 + cg*4;
    float4 r4;
    r4.x = 1.f/(1.f + expf(-(acc[0]+bb2)));
    r4.y = 1.f/(1.f + expf(-(acc[1]+bb2)));
    r4.z = 1.f/(1.f + expf(-(acc[2]+bb2)));
    r4.w = 1.f/(1.f + expf(-(acc[3]+bb2)));
    *(float4*)&refine[o] = r4;
}

// ---------------- combine (fused q-norm) ----------------
__global__ void combine_kernel(const float* __restrict__ qkv, const float* __restrict__ attnm,
                               const float* __restrict__ refine, const float* __restrict__ g1,
                               const float* __restrict__ xsca, const float* __restrict__ temp,
                               float* __restrict__ comb)
{
    int z = blockIdx.y; int b = z >> 3; int hh = z & 7;
    __shared__ float am[80];
    if (threadIdx.x < 80) am[threadIdx.x] = attnm[z*80 + threadIdx.x];
    __syncthreads();
    int n = blockIdx.x * 256 + threadIdx.x;
    float q[8]; float qs = 0.f;
    size_t qb = ((size_t)b*C3 + hh*CHD)*NN + n;
    #pragma unroll
    for (int i = 0; i < 8; i++) { q[i] = qkv[qb + i*NN]; qs += q[i]*q[i]; }
    float qsc = 1.f/(sqrtf(qs) + 1e-6f);
    #pragma unroll
    for (int i = 0; i < 8; i++) q[i] *= qsc;
    float den = (float)NN + 1e-6f;
    #pragma unroll
    for (int i = 0; i < 8; i++) den += q[i]*am[64 + i];
    float scale = __ldg(&temp[hh]) * refine[(size_t)z*NN + n] / den;
    #pragma unroll
    for (int j = 0; j < 8; j++) {
        float num = am[72 + j];
        #pragma unroll
        for (int i = 0; i < 8; i++) num += q[i]*am[i*8 + j];
        int c = hh*CHD + j;
        size_t o = ((size_t)b*CC + c)*NN + n;
        comb[o] = num * scale * __ldg(&xsca[b*CC + c]) * g1[o];
    }
}

// ---------------- launch ----------------
extern "C" void kernel_launch(void* const* d_in, const int* in_sizes, int n_in,
                              void* d_out, int out_size)
{
    const float* x      = (const float*)d_in[0];
    const float* ln1_w  = (const float*)d_in[1];
    const float* sca_w  = (const float*)d_in[2];
    const float* sca_b  = (const float*)d_in[3];
    const float* dw1_w  = (const float*)d_in[4];
    const float* dw2_w  = (const float*)d_in[5];
    const float* qkv_w  = (const float*)d_in[6];
    const float* qkv_dw = (const float*)d_in[7];
    const float* temp   = (const float*)d_in[8];
    const float* r3_w   = (const float*)d_in[9];
    const float* r3_b   = (const float*)d_in[10];
    const float* r5_w   = (const float*)d_in[11];
    const float* r5_b   = (const float*)d_in[12];
    const float* r7_w   = (const float*)d_in[13];
    const float* r7_b   = (const float*)d_in[14];
    const float* proj_w = (const float*)d_in[15];
    const float* ln2_w  = (const float*)d_in[16];
    const float* pin_w  = (const float*)d_in[17];
    const float* ffn_dw = (const float*)d_in[18];
    const float* pout_w = (const float*)d_in[19];
    float* out = (float*)d_out;

    float *py, *pxT, *pxi1, *pg1, *pbig, *pqkv, *pu, *pg2, *pref, *pmp, *pxsca, *ppart, *pattnm;
    cudaGetSymbolAddress((void**)&py,    d_y);
    cudaGetSymbolAddress((void**)&pxT,   d_xT);
    cudaGetSymbolAddress((void**)&pxi1,  d_xi1);
    cudaGetSymbolAddress((void**)&pg1,   d_g1);
    cudaGetSymbolAddress((void**)&pbig,  d_big);
    cudaGetSymbolAddress((void**)&pqkv,  d_qkv);
    cudaGetSymbolAddress((void**)&pu,    d_u);
    cudaGetSymbolAddress((void**)&pg2,   d_g2);
    cudaGetSymbolAddress((void**)&pref,  d_ref);
    cudaGetSymbolAddress((void**)&pmp,   d_meanpart);
    cudaGetSymbolAddress((void**)&pxsca, d_xsca);
    cudaGetSymbolAddress((void**)&ppart, d_attnpart);
    cudaGetSymbolAddress((void**)&pattnm,d_attnm);

    cudaFuncSetAttribute((const void*)mmagemm_kernel<CC, 1, C3,   0>, cudaFuncAttributeMaxDynamicSharedMemorySize, GEMM_SMEM);
    cudaFuncSetAttribute((const void*)mmagemm_kernel<CC, 1, C2,   0>, cudaFuncAttributeMaxDynamicSharedMemorySize, GEMM_SMEM);
    cudaFuncSetAttribute((const void*)mmagemm_kernel<CC, 1, CC,   1>, cudaFuncAttributeMaxDynamicSharedMemorySize, GEMM_SMEM);
    cudaFuncSetAttribute((const void*)mmagemm_kernel<CC, 1, HID2, 0>, cudaFuncAttributeMaxDynamicSharedMemorySize, GEMM_SMEM);
    cudaFuncSetAttribute((const void*)mmagemm_kernel<HIDD, 3, CC, 1>, cudaFuncAttributeMaxDynamicSharedMemorySize, GEMM_SMEM);
    cudaFuncSetAttribute(refine_kernel<3>, cudaFuncAttributeMaxDynamicSharedMemorySize, 16*(34*40)*4 + 16*9*4);
    cudaFuncSetAttribute(refine_kernel<5>, cudaFuncAttributeMaxDynamicSharedMemorySize, 16*(36*40)*4 + 16*25*4);
    cudaFuncSetAttribute(refine_kernel<7>, cudaFuncAttributeMaxDynamicSharedMemorySize, 16*(38*40)*4 + 16*49*4);

    // LN1 (+ transpose of input for residual)
    ln_kernel<0><<<BN/256, 256>>>(x, ln1_w, py, pxT);
    mean1_kernel<<<dim3(64, BB*CC), 256>>>(py, pmp);
    xsca_kernel<<<BB, CC>>>(pmp, sca_w, sca_b, pxsca);
    // 1x1 convs (tf32 mma.sync): qkv (192ch) and dw1 (128ch)
    mmagemm_kernel<CC, 1, C3, 0><<<dim3(NN/128, 3, BB), 256, GEMM_SMEM>>>(py, qkv_w, pbig, nullptr);
    mmagemm_kernel<CC, 1, C2, 0><<<dim3(NN/128, 2, BB), 256, GEMM_SMEM>>>(py, dw1_w, pu, nullptr);
    // depthwise 3x3 on qkv
    dw3_kernel<C3><<<dim3(8, 8, BB*C3), 256>>>(pbig, qkv_dw, pqkv);
    // grouped conv dw2 + gelu -> g1
    dw2gelu_kernel<<<dim3(8, 8, BB*CC), 256>>>(pu, dw2_w, pg1);
    // global reductions k@v, ksum, vsum (k-norm fused)
    attnred1_kernel<<<dim3(64, 32), 256>>>(pqkv, ppart);
    attnred2_kernel<<<32, 128>>>(ppart, pattnm);
    // refine conv + sigmoid (q/k-norm fused)
    refine_kernel<3><<<dim3(8, 8, BB*2), 256, 16*(34*40)*4 + 16*9*4>>>(pqkv, r3_w, r3_b, 0, 2, pref);
    refine_kernel<5><<<dim3(8, 8, BB*3), 256, 16*(36*40)*4 + 16*25*4>>>(pqkv, r5_w, r5_b, 2, 3, pref);
    refine_kernel<7><<<dim3(8, 8, BB*3), 256, 16*(38*40)*4 + 16*49*4>>>(pqkv, r7_w, r7_b, 5, 3, pref);
    // combine -> comb (reuse d_y)
    combine_kernel<<<dim3(NN/256, BB*HEADS), 256>>>(pqkv, pattnm, pref, pg1, pxsca, temp, py);
    // proj 1x1 + residual
    mmagemm_kernel<CC, 1, CC, 1><<<dim3(NN/128, 1, BB), 256, GEMM_SMEM>>>(py, proj_w, pxi1, pxT);
    // LN2
    ln_kernel<1><<<BN/256, 256>>>(pxi1, ln2_w, py, nullptr);
    // FFN: pin 64->340
    mmagemm_kernel<CC, 1, HID2, 0><<<dim3(NN/128, 6, BB), 256, GEMM_SMEM>>>(py, pin_w, pbig, nullptr);
    // FFN depthwise + gated gelu
    ffndw_kernel<<<dim3(8, 8, BB*HIDD), 256>>>(pbig, ffn_dw, pg2);
    // pout 170->64 + residual -> output (K chunks: 3x64 covering 170 w/ zero pad)
    mmagemm_kernel<HIDD, 3, CC, 1><<<dim3(NN/128, 1, BB), 256, GEMM_SMEM>>>(pg2, pout_w, out, pxi1);
}

// round 12
// speedup vs baseline: 1.4461x; 1.1411x over previous
#include <cuda_runtime.h>
#include <math.h>
#include <stdint.h>

// ---------------- constants ----------------
#define BB   4
#define CC   64
#define HH   256
#define WW   256
#define NN   65536      // HH*WW
#define HEADS 8
#define CHD  8
#define HIDD 170
#define HID2 340
#define C3   192
#define C2   128
#define BN   262144     // BB*NN

// ---------------- scratch (static device memory; allocation-free) ----------------
__device__ float d_y   [BB*CC*NN];     // combine output (proj input)
__device__ float d_xT  [BB*CC*NN];     // input transposed to (B,C,N)
__device__ float d_xi1 [BB*CC*NN];     // after attention residual
__device__ float d_g1  [BB*CC*NN];     // gelu(x1)
__device__ float d_big [BB*HID2*NN];   // qkv_pre (192ch) then FFN hidden (340ch)
__device__ float d_qkv [BB*C3*NN];     // depthwise qkv (raw; norms fused into consumers)
__device__ float d_u   [BB*C2*NN];     // dw1 out (128ch)
__device__ float d_g2  [BB*HIDD*NN];   // gated FFN hidden (170ch)
__device__ float d_ref [BB*HEADS*NN];  // sigmoid(refine)
__device__ float d_inv1[BN];           // per-pixel LN1 scale
__device__ float d_inv2[BN];           // per-pixel LN2 scale
__device__ float d_meanpart[BB*CC*64];
__device__ float d_xsca[BB*CC];
__device__ float d_attnpart[32*64*80];
__device__ float d_attnm[32*80];

__device__ __forceinline__ float gelu_exact(float x) {
    return 0.5f * x * (1.f + erff(x * 0.70710678118654752f));
}

// warp mapping: 4 rows x 8 col-groups per warp -> conflict-free LDS.128 on 40-float rows
__device__ __forceinline__ void tmap(int tid, int& row, int& cg) {
    int lane = tid & 31;
    cg  = lane & 7;
    row = ((tid >> 5) << 2) | ((lane >> 3) & 3);
}

// ---------------- tf32 helpers ----------------
__device__ __forceinline__ uint32_t f2tf32(float f) {
    uint32_t u;
    asm("cvt.rna.tf32.f32 %0, %1;" : "=r"(u) : "f"(f));
    return u;
}
__device__ __forceinline__ void mma_tf32(float c[4], const uint32_t a[4], const uint32_t b[2]) {
    asm volatile(
        "mma.sync.aligned.m16n8k8.row.col.f32.tf32.tf32.f32 "
        "{%0,%1,%2,%3},{%4,%5,%6,%7},{%8,%9},{%0,%1,%2,%3};"
        : "+f"(c[0]), "+f"(c[1]), "+f"(c[2]), "+f"(c[3])
        : "r"(a[0]), "r"(a[1]), "r"(a[2]), "r"(a[3]), "r"(b[0]), "r"(b[1]));
}

// ================= mma.sync tf32 1x1-conv GEMM =================
// D[o][n] = sum_k W[o][k] * (X[k][n] * (LN? inv[n]*lnw[k] : 1)), per batch.
// Block: 256 thr (8 warps), N tile = 128 pixels staged ONCE; loop over all
// 64-output blocks in-kernel. Warp computes 32x32 (2 m-tiles x 4 n-tiles).
#define SA 76
#define SB 136
template<int INC, int KCH, int OUT, int RESID, int LN>
__global__ void __launch_bounds__(256) mmagemm_kernel(
        const float* __restrict__ in, const float* __restrict__ w,
        float* __restrict__ out, const float* __restrict__ resid,
        const float* __restrict__ invp, const float* __restrict__ lnw)
{
    extern __shared__ uint32_t dsm[];
    uint32_t* w_s  = dsm;            // 64 x SA
    uint32_t* in_s = dsm + 64*SA;    // 64 x SB
    const int tid = threadIdx.x;
    const int wi = tid >> 5, lane = tid & 31;
    const int g = lane >> 2, q = lane & 3;
    const int wm = wi & 1, wn = wi >> 1;
    const int pix0 = blockIdx.x * 128;
    const int bz = blockIdx.z;

    if (KCH == 1) {
        // -------- stage input once (optionally LN-scaled) --------
        for (int idx = tid; idx < 64*32; idx += 256) {
            int k = idx >> 5, n = (idx & 31) * 4;
            float4 v = make_float4(0.f,0.f,0.f,0.f);
            if (k < INC) {
                v = *(const float4*)&in[((size_t)(bz*INC + k))*NN + pix0 + n];
                if (LN) {
                    float lw = __ldg(&lnw[k]);
                    float4 iv = *(const float4*)&invp[(size_t)bz*NN + pix0 + n];
                    v.x *= iv.x*lw; v.y *= iv.y*lw; v.z *= iv.z*lw; v.w *= iv.w*lw;
                }
            }
            in_s[k*SB + n + 0] = f2tf32(v.x);
            in_s[k*SB + n + 1] = f2tf32(v.y);
            in_s[k*SB + n + 2] = f2tf32(v.z);
            in_s[k*SB + n + 3] = f2tf32(v.w);
        }
        const int NOB = (OUT + 63) / 64;
        for (int ob = 0; ob < NOB; ob++) {
            const int o0 = ob * 64;
            __syncthreads();   // iter0: in_s ready; later: prior mma done with w_s
            for (int idx = tid; idx < 64*64; idx += 256) {
                int o = idx >> 6, k = idx & 63;
                float v = 0.f;
                if ((o0 + o < OUT) && (k < INC)) v = w[(size_t)(o0 + o)*INC + k];
                w_s[o*SA + k] = f2tf32(v);
            }
            __syncthreads();
            float acc[2][4][4];
            #pragma unroll
            for (int mt = 0; mt < 2; mt++)
                #pragma unroll
                for (int nt = 0; nt < 4; nt++)
                    #pragma unroll
                    for (int i = 0; i < 4; i++) acc[mt][nt][i] = 0.f;
            #pragma unroll
            for (int ks = 0; ks < 8; ks++) {
                const int k = ks*8 + q;
                uint32_t a[2][4], b[4][2];
                #pragma unroll
                for (int mt = 0; mt < 2; mt++) {
                    int o = wm*32 + mt*16 + g;
                    a[mt][0] = w_s[o*SA + k];
                    a[mt][1] = w_s[(o+8)*SA + k];
                    a[mt][2] = w_s[o*SA + k + 4];
                    a[mt][3] = w_s[(o+8)*SA + k + 4];
                }
                #pragma unroll
                for (int nt = 0; nt < 4; nt++) {
                    int n = wn*32 + nt*8 + g;
                    b[nt][0] = in_s[k*SB + n];
                    b[nt][1] = in_s[(k+4)*SB + n];
                }
                #pragma unroll
                for (int mt = 0; mt < 2; mt++)
                    #pragma unroll
                    for (int nt = 0; nt < 4; nt++)
                        mma_tf32(acc[mt][nt], a[mt], b[nt]);
            }
            #pragma unroll
            for (int mt = 0; mt < 2; mt++) {
                #pragma unroll
                for (int nt = 0; nt < 4; nt++) {
                    int o = o0 + wm*32 + mt*16 + g;
                    int n = pix0 + wn*32 + nt*8 + q*2;
                    if ((OUT % 64 == 0) || o < OUT) {
                        size_t base = ((size_t)(bz*OUT + o))*NN + n;
                        float2 v = make_float2(acc[mt][nt][0], acc[mt][nt][1]);
                        if (RESID) { float2 r = *(const float2*)&resid[base]; v.x += r.x; v.y += r.y; }
                        *(float2*)&out[base] = v;
                    }
                    if ((OUT % 64 == 0) || o + 8 < OUT) {
                        size_t base = ((size_t)(bz*OUT + o + 8))*NN + n;
                        float2 v = make_float2(acc[mt][nt][2], acc[mt][nt][3]);
                        if (RESID) { float2 r = *(const float2*)&resid[base]; v.x += r.x; v.y += r.y; }
                        *(float2*)&out[base] = v;
                    }
                }
            }
        }
    } else {
        // -------- k-chunked path (single 64-output block; pout) --------
        float acc[2][4][4];
        #pragma unroll
        for (int mt = 0; mt < 2; mt++)
            #pragma unroll
            for (int nt = 0; nt < 4; nt++)
                #pragma unroll
                for (int i = 0; i < 4; i++) acc[mt][nt][i] = 0.f;
        for (int kc = 0; kc < KCH; kc++) {
            const int k0 = kc * 64;
            __syncthreads();
            for (int idx = tid; idx < 64*64; idx += 256) {
                int o = idx >> 6, k = idx & 63;
                float v = 0.f;
                if ((o < OUT) && (k0 + k < INC)) v = w[(size_t)o*INC + k0 + k];
                w_s[o*SA + k] = f2tf32(v);
            }
            for (int idx = tid; idx < 64*32; idx += 256) {
                int k = idx >> 5, n = (idx & 31) * 4;
                float4 v = make_float4(0.f,0.f,0.f,0.f);
                if (k0 + k < INC) v = *(const float4*)&in[((size_t)(bz*INC + k0 + k))*NN + pix0 + n];
                in_s[k*SB + n + 0] = f2tf32(v.x);
                in_s[k*SB + n + 1] = f2tf32(v.y);
                in_s[k*SB + n + 2] = f2tf32(v.z);
                in_s[k*SB + n + 3] = f2tf32(v.w);
            }
            __syncthreads();
            #pragma unroll
            for (int ks = 0; ks < 8; ks++) {
                const int k = ks*8 + q;
                uint32_t a[2][4], b[4][2];
                #pragma unroll
                for (int mt = 0; mt < 2; mt++) {
                    int o = wm*32 + mt*16 + g;
                    a[mt][0] = w_s[o*SA + k];
                    a[mt][1] = w_s[(o+8)*SA + k];
                    a[mt][2] = w_s[o*SA + k + 4];
                    a[mt][3] = w_s[(o+8)*SA + k + 4];
                }
                #pragma unroll
                for (int nt = 0; nt < 4; nt++) {
                    int n = wn*32 + nt*8 + g;
                    b[nt][0] = in_s[k*SB + n];
                    b[nt][1] = in_s[(k+4)*SB + n];
                }
                #pragma unroll
                for (int mt = 0; mt < 2; mt++)
                    #pragma unroll
                    for (int nt = 0; nt < 4; nt++)
                        mma_tf32(acc[mt][nt], a[mt], b[nt]);
            }
        }
        #pragma unroll
        for (int mt = 0; mt < 2; mt++) {
            #pragma unroll
            for (int nt = 0; nt < 4; nt++) {
                int o = wm*32 + mt*16 + g;
                int n = pix0 + wn*32 + nt*8 + q*2;
                if ((OUT % 64 == 0) || o < OUT) {
                    size_t base = ((size_t)(bz*OUT + o))*NN + n;
                    float2 v = make_float2(acc[mt][nt][0], acc[mt][nt][1]);
                    if (RESID) { float2 r = *(const float2*)&resid[base]; v.x += r.x; v.y += r.y; }
                    *(float2*)&out[base] = v;
                }
                if ((OUT % 64 == 0) || o + 8 < OUT) {
                    size_t base = ((size_t)(bz*OUT + o + 8))*NN + n;
                    float2 v = make_float2(acc[mt][nt][2], acc[mt][nt][3]);
                    if (RESID) { float2 r = *(const float2*)&resid[base]; v.x += r.x; v.y += r.y; }
                    *(float2*)&out[base] = v;
                }
            }
        }
    }
}
#define GEMM_SMEM ((64*SA + 64*SB)*4)

// ---------------- LN prep: layout 0 (B,N,C input) -> xT + inv ----------------
__global__ void ln0prep_kernel(const float* __restrict__ in, float* __restrict__ xT,
                               float* __restrict__ inv)
{
    int gid = blockIdx.x * 256 + threadIdx.x;
    int b = gid >> 16;
    int n = gid & (NN - 1);
    float v[CC];
    const float4* p = reinterpret_cast<const float4*>(in + (size_t)gid * CC);
    #pragma unroll
    for (int i = 0; i < 16; i++) {
        float4 t = p[i];
        v[4*i] = t.x; v[4*i+1] = t.y; v[4*i+2] = t.z; v[4*i+3] = t.w;
    }
    float s = 0.f, s2 = 0.f;
    #pragma unroll
    for (int c = 0; c < CC; c++) { s += v[c]; s2 += v[c]*v[c]; }
    float mean = s * (1.f / CC);
    float var  = s2 * (1.f / CC) - mean * mean;
    inv[gid] = rsqrtf(var + 1e-5f);
    #pragma unroll
    for (int c = 0; c < CC; c++)
        xT[((size_t)b*CC + c)*NN + n] = v[c];
}

// ---------------- LN prep: layout 1 (B,C,N input) -> inv only ----------------
__global__ void ln1prep_kernel(const float* __restrict__ in, float* __restrict__ inv)
{
    int gid = blockIdx.x * 256 + threadIdx.x;
    int b = gid >> 16;
    int n = gid & (NN - 1);
    float s = 0.f, s2 = 0.f;
    #pragma unroll
    for (int c = 0; c < CC; c++) {
        float v = in[((size_t)b*CC + c)*NN + n];
        s += v; s2 += v*v;
    }
    float mean = s * (1.f / CC);
    float var  = s2 * (1.f / CC) - mean * mean;
    inv[gid] = rsqrtf(var + 1e-5f);
}

// ---------------- channel mean of LN1 output (stage 1; from xT*inv) ----------------
__global__ void mean1_kernel(const float* __restrict__ xT, const float* __restrict__ inv,
                             float* __restrict__ part)
{
    int chunk = blockIdx.x;
    int bc    = blockIdx.y;
    int b     = bc >> 6;
    size_t base = (size_t)bc * NN + chunk * 1024;
    size_t ibase = (size_t)b * NN + chunk * 1024;
    float s = 0.f;
    #pragma unroll
    for (int i = 0; i < 4; i++)
        s += xT[base + i*256 + threadIdx.x] * inv[ibase + i*256 + threadIdx.x];
    __shared__ float red[256];
    red[threadIdx.x] = s; __syncthreads();
    for (int off = 128; off; off >>= 1) {
        if (threadIdx.x < off) red[threadIdx.x] += red[threadIdx.x + off];
        __syncthreads();
    }
    if (threadIdx.x == 0) part[bc*64 + chunk] = red[0];
}

__global__ void xsca_kernel(const float* __restrict__ part, const float* __restrict__ sw,
                            const float* __restrict__ sb, const float* __restrict__ lnw,
                            float* __restrict__ xsca)
{
    __shared__ float m[CC];
    int b = blockIdx.x, c = threadIdx.x;
    float s = 0.f;
    for (int k = 0; k < 64; k++) s += part[(b*CC + c)*64 + k];
    m[c] = s * (1.f / NN) * __ldg(&lnw[c]);
    __syncthreads();
    float a = __ldg(&sb[c]);
    for (int i = 0; i < CC; i++) a += __ldg(&sw[c*CC + i]) * m[i];
    xsca[b*CC + c] = a;
}

// ---------------- depthwise 3x3 (pad 1), 32x32 tile, 4 cols/thread ----------------
template<int NCH>
__global__ void dw3_kernel(const float* __restrict__ in, const float* __restrict__ w,
                           float* __restrict__ out)
{
    int z = blockIdx.z; int b = z / NCH; int ch = z - b*NCH;
    const float* plane = in + ((size_t)b*NCH + ch) * NN;
    __shared__ float raw[34*40];
    int row, cg; tmap(threadIdx.x, row, cg);
    int gx0 = blockIdx.x * 32, gy0 = blockIdx.y * 32;
    for (int idx = threadIdx.x; idx < 34*34; idx += 256) {
        int r = idx / 34, c = idx - r*34;
        int gy = gy0 - 1 + r, gx = gx0 - 1 + c;
        raw[r*40 + c] = (gy >= 0 && gy < HH && gx >= 0 && gx < WW) ? plane[gy*WW + gx] : 0.f;
    }
    float wr[9];
    #pragma unroll
    for (int i = 0; i < 9; i++) wr[i] = __ldg(&w[ch*9 + i]);
    __syncthreads();
    float acc[4] = {0.f,0.f,0.f,0.f};
    #pragma unroll
    for (int ky = 0; ky < 3; ky++) {
        const float4* rp = (const float4*)&raw[(row+ky)*40 + cg*4];
        float f[8];
        *(float4*)&f[0] = rp[0]; *(float4*)&f[4] = rp[1];
        #pragma unroll
        for (int kx = 0; kx < 3; kx++)
            #pragma unroll
            for (int cx = 0; cx < 4; cx++) acc[cx] += wr[ky*3+kx]*f[cx+kx];
    }
    size_t o = ((size_t)b*NCH + ch)*NN + (size_t)(gy0+row)*WW + gx0 + cg*4;
    *(float4*)&out[o] = make_float4(acc[0],acc[1],acc[2],acc[3]);
}

// ---------------- grouped conv dw2 (2 in / 1 out per group) + GELU ----------------
__global__ void dw2gelu_kernel(const float* __restrict__ u, const float* __restrict__ w,
                               float* __restrict__ g1)
{
    int z = blockIdx.z; int b = z / CC; int c = z - b*CC;
    __shared__ float raw[2][34*40];
    int row, cg; tmap(threadIdx.x, row, cg);
    int gx0 = blockIdx.x * 32, gy0 = blockIdx.y * 32;
    for (int idx = threadIdx.x; idx < 2*34*34; idx += 256) {
        int j = idx / (34*34); int rem = idx - j*34*34;
        int r = rem / 34, cc2 = rem - r*34;
        int gy = gy0 - 1 + r, gx = gx0 - 1 + cc2;
        raw[j][r*40 + cc2] = (gy >= 0 && gy < HH && gx >= 0 && gx < WW)
                             ? u[((size_t)b*C2 + 2*c + j)*NN + gy*WW + gx] : 0.f;
    }
    float wr[2][9];
    #pragma unroll
    for (int j = 0; j < 2; j++)
        #pragma unroll
        for (int i = 0; i < 9; i++) wr[j][i] = __ldg(&w[(c*2 + j)*9 + i]);
    __syncthreads();
    float acc[4] = {0.f,0.f,0.f,0.f};
    #pragma unroll
    for (int j = 0; j < 2; j++)
        #pragma unroll
        for (int ky = 0; ky < 3; ky++) {
            const float4* rp = (const float4*)&raw[j][(row+ky)*40 + cg*4];
            float f[8];
            *(float4*)&f[0] = rp[0]; *(float4*)&f[4] = rp[1];
            #pragma unroll
            for (int kx = 0; kx < 3; kx++)
                #pragma unroll
                for (int cx = 0; cx < 4; cx++) acc[cx] += wr[j][ky*3+kx]*f[cx+kx];
        }
    size_t o = ((size_t)b*CC + c)*NN + (size_t)(gy0+row)*WW + gx0 + cg*4;
    *(float4*)&g1[o] = make_float4(gelu_exact(acc[0]),gelu_exact(acc[1]),
                                   gelu_exact(acc[2]),gelu_exact(acc[3]));
}

// ---------------- FFN depthwise 3x3 + gated GELU ----------------
__global__ void ffndw_kernel(const float* __restrict__ h, const float* __restrict__ w,
                             float* __restrict__ g2)
{
    int z = blockIdx.z; int b = z / HIDD; int i = z - b*HIDD;
    const float* p0 = h + ((size_t)b*HID2 + i) * NN;
    const float* p1 = h + ((size_t)b*HID2 + HIDD + i) * NN;
    __shared__ float raw[2][34*40];
    int row, cg; tmap(threadIdx.x, row, cg);
    int gx0 = blockIdx.x * 32, gy0 = blockIdx.y * 32;
    for (int idx = threadIdx.x; idx < 2*34*34; idx += 256) {
        int j = idx / (34*34); int rem = idx - j*34*34;
        int r = rem / 34, cc2 = rem - r*34;
        int gy = gy0 - 1 + r, gx = gx0 - 1 + cc2;
        const float* pl = j ? p1 : p0;
        raw[j][r*40 + cc2] = (gy >= 0 && gy < HH && gx >= 0 && gx < WW) ? pl[gy*WW + gx] : 0.f;
    }
    float w0[9], w1[9];
    #pragma unroll
    for (int t = 0; t < 9; t++) { w0[t] = __ldg(&w[i*9 + t]); w1[t] = __ldg(&w[(HIDD+i)*9 + t]); }
    __syncthreads();
    float a0[4] = {0.f,0.f,0.f,0.f}, a1[4] = {0.f,0.f,0.f,0.f};
    #pragma unroll
    for (int ky = 0; ky < 3; ky++) {
        const float4* rp0 = (const float4*)&raw[0][(row+ky)*40 + cg*4];
        const float4* rp1 = (const float4*)&raw[1][(row+ky)*40 + cg*4];
        float f0[8], f1[8];
        *(float4*)&f0[0] = rp0[0]; *(float4*)&f0[4] = rp0[1];
        *(float4*)&f1[0] = rp1[0]; *(float4*)&f1[4] = rp1[1];
        #pragma unroll
        for (int kx = 0; kx < 3; kx++)
            #pragma unroll
            for (int cx = 0; cx < 4; cx++) {
                a0[cx] += w0[ky*3+kx]*f0[cx+kx];
                a1[cx] += w1[ky*3+kx]*f1[cx+kx];
            }
    }
    size_t o = ((size_t)b*HIDD + i)*NN + (size_t)(gy0+row)*WW + gx0 + cg*4;
    *(float4*)&g2[o] = make_float4(gelu_exact(a0[0])*a1[0], gelu_exact(a0[1])*a1[1],
                                   gelu_exact(a0[2])*a1[2], gelu_exact(a0[3])*a1[3]);
}

// ---------------- attention reductions (k@v, ksum, vsum) with fused k-norm ----------------
__global__ void attnred1_kernel(const float* __restrict__ qkv, float* __restrict__ part)
{
    int bh = blockIdx.y; int b = bh >> 3; int hh = bh & 7;
    int chunk = blockIdx.x;
    size_t kb = ((size_t)b*C3 + CC + hh*CHD)*NN;
    size_t vb = ((size_t)b*C3 + 2*CC + hh*CHD)*NN;
    float kv[8][8]; float ks[8]; float vs[8];
    #pragma unroll
    for (int i = 0; i < 8; i++) {
        ks[i] = 0.f; vs[i] = 0.f;
        #pragma unroll
        for (int j = 0; j < 8; j++) kv[i][j] = 0.f;
    }
    for (int it = 0; it < 4; it++) {
        int n = chunk*1024 + it*256 + threadIdx.x;
        float kk[8], vv[8]; float ks2 = 0.f;
        #pragma unroll
        for (int i = 0; i < 8; i++) {
            kk[i] = qkv[kb + i*NN + n]; ks2 += kk[i]*kk[i];
            vv[i] = qkv[vb + i*NN + n];
        }
        float ksc = 1.f / (sqrtf(ks2) + 1e-6f);
        #pragma unroll
        for (int i = 0; i < 8; i++) {
            kk[i] *= ksc;
            ks[i] += kk[i]; vs[i] += vv[i];
            #pragma unroll
            for (int j = 0; j < 8; j++) kv[i][j] += kk[i]*vv[j];
        }
    }
    __shared__ float red[8][80];
    int lane = threadIdx.x & 31, wid = threadIdx.x >> 5;
    #pragma unroll
    for (int idx = 0; idx < 80; idx++) {
        float v;
        if (idx < 64) v = kv[idx >> 3][idx & 7];
        else if (idx < 72) v = ks[idx - 64];
        else v = vs[idx - 72];
        #pragma unroll
        for (int off = 16; off; off >>= 1) v += __shfl_down_sync(0xffffffffu, v, off);
        if (lane == 0) red[wid][idx] = v;
    }
    __syncthreads();
    if (threadIdx.x < 80) {
        float s = 0.f;
        #pragma unroll
        for (int w2 = 0; w2 < 8; w2++) s += red[w2][threadIdx.x];
        part[((size_t)bh*64 + chunk)*80 + threadIdx.x] = s;
    }
}

__global__ void attnred2_kernel(const float* __restrict__ part, float* __restrict__ attnm)
{
    int bh = blockIdx.x; int t = threadIdx.x;
    if (t < 80) {
        float s = 0.f;
        for (int c2 = 0; c2 < 64; c2++) s += part[((size_t)bh*64 + c2)*80 + t];
        attnm[bh*80 + t] = s;
    }
}

// ---------------- multi-window refine conv + sigmoid (fused q/k norm) ----------------
template<int WS>
__global__ void refine_kernel(const float* __restrict__ qkv, const float* __restrict__ w,
                              const float* __restrict__ bias, int head0, int nh,
                              float* __restrict__ refine)
{
    constexpr int R  = WS/2;
    constexpr int RR = 32 + 2*R;
    constexpr int PS = RR*40;
    extern __shared__ float sm[];
    float* wsm = sm + 16*PS;
    int z = blockIdx.z; int b = z / nh; int hw = z - b*nh; int hh = head0 + hw;
    int row, cg; tmap(threadIdx.x, row, cg);
    int gx0 = blockIdx.x*32, gy0 = blockIdx.y*32;
    for (int idx = threadIdx.x; idx < 16*RR*RR; idx += 256) {
        int ci = idx / (RR*RR); int rem = idx - ci*RR*RR;
        int r = rem / RR, c = rem - r*RR;
        int gy = gy0 - R + r, gx = gx0 - R + c;
        int chan = (ci < 8) ? (hh*CHD + ci) : (CC + hh*CHD + ci - 8);
        sm[ci*PS + r*40 + c] = (gy >= 0 && gy < HH && gx >= 0 && gx < WW)
                               ? qkv[((size_t)b*C3 + chan)*NN + gy*WW + gx] : 0.f;
    }
    for (int idx = threadIdx.x; idx < 16*WS*WS; idx += 256)
        wsm[idx] = __ldg(&w[hw*16*WS*WS + idx]);
    __syncthreads();
    for (int p = threadIdx.x; p < RR*RR; p += 256) {
        int r = p / RR, c = p - r*RR;
        int off = r*40 + c;
        float qv[8], kvv[8]; float qs = 0.f, ks2 = 0.f;
        #pragma unroll
        for (int i = 0; i < 8; i++) {
            qv[i] = sm[i*PS + off]; qs += qv[i]*qv[i];
            kvv[i] = sm[(8+i)*PS + off]; ks2 += kvv[i]*kvv[i];
        }
        float qsc = 1.f/(sqrtf(qs) + 1e-6f);
        float ksc = 1.f/(sqrtf(ks2) + 1e-6f);
        #pragma unroll
        for (int i = 0; i < 8; i++) {
            sm[i*PS + off] = qv[i]*qsc;
            sm[(8+i)*PS + off] = kvv[i]*ksc;
        }
    }
    __syncthreads();
    float acc[4] = {0.f,0.f,0.f,0.f};
    for (int ci = 0; ci < 16; ci++) {
        const float* pl = sm + ci*PS;
        #pragma unroll
        for (int ky = 0; ky < WS; ky++) {
            const float4* rp = (const float4*)&pl[(row+ky)*40 + cg*4];
            float f[12];
            *(float4*)&f[0] = rp[0]; *(float4*)&f[4] = rp[1];
            if (WS + 3 > 8) *(float4*)&f[8] = rp[2];
            #pragma unroll
            for (int kx = 0; kx < WS; kx++) {
                float wv = wsm[ci*WS*WS + ky*WS + kx];
                #pragma unroll
                for (int cx = 0; cx < 4; cx++) acc[cx] += wv*f[cx+kx];
            }
        }
    }
    float bb2 = __ldg(&bias[hw]);
    size_t o = ((size_t)(b*HEADS + hh))*NN + (size_t)(gy0+row)*WW + gx0 + cg*4;
    float4 r4;
    r4.x = 1.f/(1.f + expf(-(acc[0]+bb2)));
    r4.y = 1.f/(1.f + expf(-(acc[1]+bb2)));
    r4.z = 1.f/(1.f + expf(-(acc[2]+bb2)));
    r4.w = 1.f/(1.f + expf(-(acc[3]+bb2)));
    *(float4*)&refine[o] = r4;
}

// ---------------- combine (fused q-norm) ----------------
__global__ void combine_kernel(const float* __restrict__ qkv, const float* __restrict__ attnm,
                               const float* __restrict__ refine, const float* __restrict__ g1,
                               const float* __restrict__ xsca, const float* __restrict__ temp,
                               float* __restrict__ comb)
{
    int z = blockIdx.y; int b = z >> 3; int hh = z & 7;
    __shared__ float am[80];
    if (threadIdx.x < 80) am[threadIdx.x] = attnm[z*80 + threadIdx.x];
    __syncthreads();
    int n = blockIdx.x * 256 + threadIdx.x;
    float q[8]; float qs = 0.f;
    size_t qb = ((size_t)b*C3 + hh*CHD)*NN + n;
    #pragma unroll
    for (int i = 0; i < 8; i++) { q[i] = qkv[qb + i*NN]; qs += q[i]*q[i]; }
    float qsc = 1.f/(sqrtf(qs) + 1e-6f);
    #pragma unroll
    for (int i = 0; i < 8; i++) q[i] *= qsc;
    float den = (float)NN + 1e-6f;
    #pragma unroll
    for (int i = 0; i < 8; i++) den += q[i]*am[64 + i];
    float scale = __ldg(&temp[hh]) * refine[(size_t)z*NN + n] / den;
    #pragma unroll
    for (int j = 0; j < 8; j++) {
        float num = am[72 + j];
        #pragma unroll
        for (int i = 0; i < 8; i++) num += q[i]*am[i*8 + j];
        int c = hh*CHD + j;
        size_t o = ((size_t)b*CC + c)*NN + n;
        comb[o] = num * scale * __ldg(&xsca[b*CC + c]) * g1[o];
    }
}

// ---------------- launch ----------------
extern "C" void kernel_launch(void* const* d_in, const int* in_sizes, int n_in,
                              void* d_out, int out_size)
{
    const float* x      = (const float*)d_in[0];
    const float* ln1_w  = (const float*)d_in[1];
    const float* sca_w  = (const float*)d_in[2];
    const float* sca_b  = (const float*)d_in[3];
    const float* dw1_w  = (const float*)d_in[4];
    const float* dw2_w  = (const float*)d_in[5];
    const float* qkv_w  = (const float*)d_in[6];
    const float* qkv_dw = (const float*)d_in[7];
    const float* temp   = (const float*)d_in[8];
    const float* r3_w   = (const float*)d_in[9];
    const float* r3_b   = (const float*)d_in[10];
    const float* r5_w   = (const float*)d_in[11];
    const float* r5_b   = (const float*)d_in[12];
    const float* r7_w   = (const float*)d_in[13];
    const float* r7_b   = (const float*)d_in[14];
    const float* proj_w = (const float*)d_in[15];
    const float* ln2_w  = (const float*)d_in[16];
    const float* pin_w  = (const float*)d_in[17];
    const float* ffn_dw = (const float*)d_in[18];
    const float* pout_w = (const float*)d_in[19];
    float* out = (float*)d_out;

    float *py, *pxT, *pxi1, *pg1, *pbig, *pqkv, *pu, *pg2, *pref, *pinv1, *pinv2,
          *pmp, *pxsca, *ppart, *pattnm;
    cudaGetSymbolAddress((void**)&py,    d_y);
    cudaGetSymbolAddress((void**)&pxT,   d_xT);
    cudaGetSymbolAddress((void**)&pxi1,  d_xi1);
    cudaGetSymbolAddress((void**)&pg1,   d_g1);
    cudaGetSymbolAddress((void**)&pbig,  d_big);
    cudaGetSymbolAddress((void**)&pqkv,  d_qkv);
    cudaGetSymbolAddress((void**)&pu,    d_u);
    cudaGetSymbolAddress((void**)&pg2,   d_g2);
    cudaGetSymbolAddress((void**)&pref,  d_ref);
    cudaGetSymbolAddress((void**)&pinv1, d_inv1);
    cudaGetSymbolAddress((void**)&pinv2, d_inv2);
    cudaGetSymbolAddress((void**)&pmp,   d_meanpart);
    cudaGetSymbolAddress((void**)&pxsca, d_xsca);
    cudaGetSymbolAddress((void**)&ppart, d_attnpart);
    cudaGetSymbolAddress((void**)&pattnm,d_attnm);

    cudaFuncSetAttribute((const void*)mmagemm_kernel<CC, 1, C3,   0, 1>, cudaFuncAttributeMaxDynamicSharedMemorySize, GEMM_SMEM);
    cudaFuncSetAttribute((const void*)mmagemm_kernel<CC, 1, C2,   0, 1>, cudaFuncAttributeMaxDynamicSharedMemorySize, GEMM_SMEM);
    cudaFuncSetAttribute((const void*)mmagemm_kernel<CC, 1, CC,   1, 0>, cudaFuncAttributeMaxDynamicSharedMemorySize, GEMM_SMEM);
    cudaFuncSetAttribute((const void*)mmagemm_kernel<CC, 1, HID2, 0, 1>, cudaFuncAttributeMaxDynamicSharedMemorySize, GEMM_SMEM);
    cudaFuncSetAttribute((const void*)mmagemm_kernel<HIDD, 3, CC, 1, 0>, cudaFuncAttributeMaxDynamicSharedMemorySize, GEMM_SMEM);
    cudaFuncSetAttribute(refine_kernel<3>, cudaFuncAttributeMaxDynamicSharedMemorySize, 16*(34*40)*4 + 16*9*4);
    cudaFuncSetAttribute(refine_kernel<5>, cudaFuncAttributeMaxDynamicSharedMemorySize, 16*(36*40)*4 + 16*25*4);
    cudaFuncSetAttribute(refine_kernel<7>, cudaFuncAttributeMaxDynamicSharedMemorySize, 16*(38*40)*4 + 16*49*4);

    // LN1 prep: xT + inv1 (no y materialization)
    ln0prep_kernel<<<BN/256, 256>>>(x, pxT, pinv1);
    mean1_kernel<<<dim3(64, BB*CC), 256>>>(pxT, pinv1, pmp);
    xsca_kernel<<<BB, CC>>>(pmp, sca_w, sca_b, ln1_w, pxsca);
    // 1x1 convs (tf32 mma.sync, LN fused in staging, o-loop in-kernel)
    mmagemm_kernel<CC, 1, C3, 0, 1><<<dim3(NN/128, 1, BB), 256, GEMM_SMEM>>>(pxT, qkv_w, pbig, nullptr, pinv1, ln1_w);
    mmagemm_kernel<CC, 1, C2, 0, 1><<<dim3(NN/128, 1, BB), 256, GEMM_SMEM>>>(pxT, dw1_w, pu, nullptr, pinv1, ln1_w);
    // depthwise 3x3 on qkv
    dw3_kernel<C3><<<dim3(8, 8, BB*C3), 256>>>(pbig, qkv_dw, pqkv);
    // grouped conv dw2 + gelu -> g1
    dw2gelu_kernel<<<dim3(8, 8, BB*CC), 256>>>(pu, dw2_w, pg1);
    // global reductions k@v, ksum, vsum (k-norm fused)
    attnred1_kernel<<<dim3(64, 32), 256>>>(pqkv, ppart);
    attnred2_kernel<<<32, 128>>>(ppart, pattnm);
    // refine conv + sigmoid (q/k-norm fused)
    refine_kernel<3><<<dim3(8, 8, BB*2), 256, 16*(34*40)*4 + 16*9*4>>>(pqkv, r3_w, r3_b, 0, 2, pref);
    refine_kernel<5><<<dim3(8, 8, BB*3), 256, 16*(36*40)*4 + 16*25*4>>>(pqkv, r5_w, r5_b, 2, 3, pref);
    refine_kernel<7><<<dim3(8, 8, BB*3), 256, 16*(38*40)*4 + 16*49*4>>>(pqkv, r7_w, r7_b, 5, 3, pref);
    // combine -> comb (reuse d_y)
    combine_kernel<<<dim3(NN/256, BB*HEADS), 256>>>(pqkv, pattnm, pref, pg1, pxsca, temp, py);
    // proj 1x1 + residual (xT)
    mmagemm_kernel<CC, 1, CC, 1, 0><<<dim3(NN/128, 1, BB), 256, GEMM_SMEM>>>(py, proj_w, pxi1, pxT, nullptr, nullptr);
    // LN2 prep: inv2 only
    ln1prep_kernel<<<BN/256, 256>>>(pxi1, pinv2);
    // FFN: pin 64->340 (LN2 fused)
    mmagemm_kernel<CC, 1, HID2, 0, 1><<<dim3(NN/128, 1, BB), 256, GEMM_SMEM>>>(pxi1, pin_w, pbig, nullptr, pinv2, ln2_w);
    // FFN depthwise + gated gelu
    ffndw_kernel<<<dim3(8, 8, BB*HIDD), 256>>>(pbig, ffn_dw, pg2);
    // pout 170->64 + residual -> output (3 k-chunks)
    mmagemm_kernel<HIDD, 3, CC, 1, 0><<<dim3(NN/128, 1, BB), 256, GEMM_SMEM>>>(pg2, pout_w, out, pxi1, nullptr, nullptr);
}